// round 14
// baseline (speedup 1.0000x reference)
#include <cuda_runtime.h>
#include <cuda_fp16.h>
#include <cstdint>

// ---------------- problem constants ----------------
#define BN 8192
#define DD 128
#define TMARGIN 1.0f

// ---------------- tiling (round-12 proven geometry) ----------------
#define TI 128
#define TJ 64
// Lower-triangle tile enumeration: for i-tile `it`, j-tiles 0..2it+1.
#define TOTAL_TILES 4160
#define GRIDN 444                  // 148 SMs x 3 CTAs (exactly resident)
#define PITCH 272                  // 256B data + 16B pad -> conflict-free ldmatrix
#define ATILEB (128 * PITCH)       // 34816
#define BTILEB (TJ * PITCH)        // 17408
#define NTHREADS 256
#define FINF 0x7f800000u
#define BCAP 32                    // bucket capacity (mean occupancy 8)

// ---------------- device globals ----------------
__device__ float        g_sq[BN];
__device__ unsigned int g_negmin[BN];
__device__ float        g_total;
__device__ int          g_count;
__device__ int          g_lab32[BN];
__device__ __half       g_H[BN * DD];
__device__ int          g_bcnt[1024];           // zero-init; re-zeroed each run in phase 2
__device__ int          g_bmem[1024 * BCAP];
__device__ int          g_bar1;
__device__ int          g_bar2;

// ---------------- PTX helpers (baseline, legal at target sm_103) ----------------
__device__ __forceinline__ uint32_t smem_u32(const void* p) {
    uint32_t a;
    asm("{ .reg .u64 t; cvta.to.shared.u64 t, %1; cvt.u32.u64 %0, t; }" : "=r"(a) : "l"(p));
    return a;
}
#define CP_ASYNC16(dst, src) \
    asm volatile("cp.async.cg.shared.global [%0], [%1], 16;" :: "r"(dst), "l"(src))
#define CP_COMMIT() asm volatile("cp.async.commit_group;")
#define CP_WAIT1()  asm volatile("cp.async.wait_group 1;")
#define CP_WAIT0()  asm volatile("cp.async.wait_group 0;")

#define LDSM_X4(r0, r1, r2, r3, addr) \
    asm volatile("ldmatrix.sync.aligned.m8n8.x4.shared.b16 {%0,%1,%2,%3}, [%4];" \
                 : "=r"(r0), "=r"(r1), "=r"(r2), "=r"(r3) : "r"(addr))

#define MMA16816(d, a0, a1, a2, a3, b0, b1) \
    asm volatile("mma.sync.aligned.m16n8k16.row.col.f32.f16.f16.f32 " \
                 "{%0,%1,%2,%3}, {%4,%5,%6,%7}, {%8,%9}, {%0,%1,%2,%3};" \
                 : "+f"((d)[0]), "+f"((d)[1]), "+f"((d)[2]), "+f"((d)[3]) \
                 : "r"(a0), "r"(a1), "r"(a2), "r"(a3), "r"(b0), "r"(b1))

// ---------------- SMEM layout ----------------
#define OFF_A    0
#define OFF_B    ATILEB                      // 2 buffers of BTILEB
#define OFF_SQJ  (ATILEB + 2 * BTILEB)       // float [2][TJ]
#define OFF_LABJ (OFF_SQJ + 2 * TJ * 4)      // int   [2][TJ]
#define OFF_SMIN (OFF_LABJ + 2 * TJ * 4)     // uint  [128]   (row mins)
#define OFF_CMIN (OFF_SMIN + 512)            // uint  [2][TJ] (col mins, ping-pong)
#define SMEM_TOTAL (OFF_CMIN + 2 * TJ * 4 + 16)   // ~71.2 KB -> 3 CTAs/SM

// ---------------- fused setup: labels + buckets + fp16 convert + row norms ----------------
__global__ void setup_kernel(const float* __restrict__ E, const void* __restrict__ labraw) {
    __shared__ int s_any;
    if (threadIdx.x == 0) s_any = 0;
    __syncthreads();
    // dtype detection: int64 labels < 1024 => odd 32-bit words of first 128 pairs all 0
    if (threadIdx.x < 128) {
        int v = ((const int*)labraw)[2 * threadIdx.x + 1];
        unsigned any = __ballot_sync(0xffffffffu, v != 0);
        if ((threadIdx.x & 31) == 0 && any) atomicOr(&s_any, 1);
    }

    // one warp per row: convert + squared norm
    const int warp = threadIdx.x >> 5, lane = threadIdx.x & 31;
    const int row = blockIdx.x * 8 + warp;
    const float* r = E + (size_t)row * DD;
    __half* h = g_H + (size_t)row * DD;
    float s = 0.f;
#pragma unroll
    for (int q = 0; q < 4; q++) {
        float v = r[lane + 32 * q];
        h[lane + 32 * q] = __float2half(v);
        s += v * v;
    }
#pragma unroll
    for (int off = 16; off; off >>= 1) s += __shfl_xor_sync(0xffffffffu, s, off);
    if (lane == 0) g_sq[row] = s;

    __syncthreads();
    const int is64 = (s_any == 0);
    if (threadIdx.x < 8) {
        int i = blockIdx.x * 8 + threadIdx.x;
        g_negmin[i] = FINF;
        int lab = is64 ? (int)((const long long*)labraw)[i] : ((const int*)labraw)[i];
        g_lab32[i] = lab;
        // bucket insert (g_bcnt zeroed by previous run's phase 2 / static init)
        int b = lab & 1023;
        int slot = atomicAdd(&g_bcnt[b], 1);
        if (slot < BCAP) g_bmem[b * BCAP + slot] = i;
    }
    if (blockIdx.x == 0 && threadIdx.x == 0) {
        g_total = 0.f; g_count = 0; g_bar1 = 0; g_bar2 = 0;
    }
}

// ---------------- HMMA fused Gram + row/col masked-min + finalize ----------------
__global__ __launch_bounds__(NTHREADS, 3) void negmine_kernel(float* out, int out_size) {
    extern __shared__ char smem[];
    const uint32_t sb = smem_u32(smem);
    const int tid = threadIdx.x;
    const int w = tid >> 5, lane = tid & 31;
    const int g = lane >> 2, t4 = lane & 3;

    const int mrow0 = (w & 3) * 32;
    const int ncol0 = (w >> 2) * 32;

    const int blk = blockIdx.x;
    const int t0 = (TOTAL_TILES * blk) / GRIDN;
    const int t1 = (TOTAL_TILES * (blk + 1)) / GRIDN;

    float* sqj_all  = reinterpret_cast<float*>(smem + OFF_SQJ);
    int*   labj_all = reinterpret_cast<int*>(smem + OFF_LABJ);
    unsigned* smin  = reinterpret_cast<unsigned*>(smem + OFF_SMIN);
    unsigned* scol  = reinterpret_cast<unsigned*>(smem + OFF_CMIN);

    // decode i-tile of t0: it*(it+1) <= t0 < (it+1)*(it+2)
    int it = (int)((sqrtf(4.0f * (float)t0 + 1.0f) - 1.0f) * 0.5f);
    while ((it + 1) * (it + 2) <= t0) it++;
    while (it * (it + 1) > t0) it--;
    int i0 = it * TI;

    // ---- prologue: A(it) + B(t0) ----
#pragma unroll
    for (int c = tid; c < 2048; c += NTHREADS) {
        int row = c >> 4, col = c & 15;
        CP_ASYNC16(sb + OFF_A + row * PITCH + col * 16,
                   (const void*)(g_H + (size_t)(i0 + row) * DD + col * 8));
    }
    {
        const int j0 = (t0 - it * (it + 1)) * TJ;
#pragma unroll
        for (int c = tid; c < 1024; c += NTHREADS) {
            int row = c >> 4, col = c & 15;
            CP_ASYNC16(sb + OFF_B + row * PITCH + col * 16,
                       (const void*)(g_H + (size_t)(j0 + row) * DD + col * 8));
        }
        CP_COMMIT();
        if (tid < TJ) {
            sqj_all[tid]  = g_sq[j0 + tid];
            labj_all[tid] = g_lab32[j0 + tid];
        }
    }
    if (tid < 128) smin[tid] = FINF;
    if (tid < 2 * TJ) scol[tid] = FINF;
    CP_WAIT0();
    __syncthreads();

    // ---- per-lane ldmatrix bases ----
    uint32_t abase[2];
#pragma unroll
    for (int mf = 0; mf < 2; mf++)
        abase[mf] = sb + OFF_A
                  + (uint32_t)((mrow0 + mf * 16 + ((lane >> 3) & 1) * 8 + (lane & 7)) * PITCH)
                  + (uint32_t)((lane >> 4) * 16);
    uint32_t bbase[2];
#pragma unroll
    for (int p = 0; p < 2; p++)
        bbase[p] = sb + OFF_B
                 + (uint32_t)((ncol0 + p * 16 + ((lane >> 4) & 1) * 8 + (lane & 7)) * PITCH)
                 + (uint32_t)(((lane >> 3) & 1) * 16);

    // ---- per-i row constants ----
    float si[4]; int li[4];
#pragma unroll
    for (int mf = 0; mf < 2; mf++)
#pragma unroll
        for (int hh = 0; hh < 2; hh++) {
            int r = mrow0 + mf * 16 + hh * 8 + g;
            si[mf * 2 + hh] = g_sq[i0 + r];
            li[mf * 2 + hh] = g_lab32[i0 + r];
        }
    float rmin[4];
#pragma unroll
    for (int h = 0; h < 4; h++) rmin[h] = __int_as_float(FINF);

    // ---- phase 1: persistent mining loop ----
    for (int t = t0; t < t1; t++) {
        const int b0 = (t - t0) & 1;
        const int jt = t - it * (it + 1);
        const int j0 = jt * TJ;
        const bool last = (t + 1 == t1);
        const bool ichange = !last && (t + 1 == (it + 1) * (it + 2));

        // [1] prefetch next B
        if (!last) {
            const int b1 = b0 ^ 1;
            const int itn = ichange ? it + 1 : it;
            const int j1 = ((t + 1) - itn * (itn + 1)) * TJ;
#pragma unroll
            for (int c = tid; c < 1024; c += NTHREADS) {
                int row = c >> 4, col = c & 15;
                CP_ASYNC16(sb + OFF_B + b1 * BTILEB + row * PITCH + col * 16,
                           (const void*)(g_H + (size_t)(j1 + row) * DD + col * 8));
            }
            CP_COMMIT();
            if (tid < TJ) {
                sqj_all[b1 * TJ + tid]  = g_sq[j1 + tid];
                labj_all[b1 * TJ + tid] = g_lab32[j1 + tid];
            }
            CP_WAIT1();
        } else {
            CP_WAIT0();
        }
        __syncthreads();   // B(t) visible to all; prefetch writes published

        // [2] compute: 8 k-steps x (2A + 2B LDSM, 8 MMA)
        float acc[2][4][4];
#pragma unroll
        for (int mf = 0; mf < 2; mf++)
#pragma unroll
            for (int nf = 0; nf < 4; nf++)
#pragma unroll
                for (int e = 0; e < 4; e++) acc[mf][nf][e] = 0.f;

        const uint32_t bufoff = (uint32_t)(b0 * BTILEB);
#pragma unroll
        for (int ks = 0; ks < DD / 16; ks++) {
            uint32_t a0[4], a1[4], bf[2][4];
            LDSM_X4(a0[0], a0[1], a0[2], a0[3], abase[0] + ks * 32);
            LDSM_X4(a1[0], a1[1], a1[2], a1[3], abase[1] + ks * 32);
            LDSM_X4(bf[0][0], bf[0][1], bf[0][2], bf[0][3], bbase[0] + bufoff + ks * 32);
            LDSM_X4(bf[1][0], bf[1][1], bf[1][2], bf[1][3], bbase[1] + bufoff + ks * 32);
#pragma unroll
            for (int nf = 0; nf < 4; nf++) {
                MMA16816(acc[0][nf], a0[0], a0[1], a0[2], a0[3],
                         bf[nf >> 1][(nf & 1) * 2], bf[nf >> 1][(nf & 1) * 2 + 1]);
                MMA16816(acc[1][nf], a1[0], a1[1], a1[2], a1[3],
                         bf[nf >> 1][(nf & 1) * 2], bf[nf >> 1][(nf & 1) * 2 + 1]);
            }
        }

        // [3] epilogue: branch-free masked row/col min (positives handled in phase 2)
        const float2* sqj2  = reinterpret_cast<const float2*>(sqj_all + b0 * TJ);
        const int2*   labj2 = reinterpret_cast<const int2*>(labj_all + b0 * TJ);
        const float INF = __int_as_float(FINF);
        float cmin[8];
#pragma unroll
        for (int k = 0; k < 8; k++) cmin[k] = INF;

#pragma unroll
        for (int nf = 0; nf < 4; nf++) {
            const int c0 = ncol0 + nf * 8 + 2 * t4;
            const float2 q = sqj2[c0 >> 1];
            const int2  lb = labj2[c0 >> 1];
#pragma unroll
            for (int mf = 0; mf < 2; mf++)
#pragma unroll
                for (int hh = 0; hh < 2; hh++) {
                    const int ri = mf * 2 + hh;
                    float dd0 = fmaf(acc[mf][nf][hh * 2 + 0], -2.0f, si[ri] + q.x);
                    float dd1 = fmaf(acc[mf][nf][hh * 2 + 1], -2.0f, si[ri] + q.y);
                    float v0 = (lb.x != li[ri]) ? dd0 : INF;
                    float v1 = (lb.y != li[ri]) ? dd1 : INF;
                    rmin[ri] = fminf(rmin[ri], fminf(v0, v1));
                    cmin[nf * 2]     = fminf(cmin[nf * 2], v0);
                    cmin[nf * 2 + 1] = fminf(cmin[nf * 2 + 1], v1);
                }
        }

        // column reduce across the 8 g-lanes sharing each column
#pragma unroll
        for (int k = 0; k < 8; k++) {
            float v = cmin[k];
            v = fminf(v, __shfl_xor_sync(0xffffffffu, v, 4));
            v = fminf(v, __shfl_xor_sync(0xffffffffu, v, 8));
            v = fminf(v, __shfl_xor_sync(0xffffffffu, v, 16));
            cmin[k] = v;
        }
        if (lane < 4) {
#pragma unroll
            for (int k = 0; k < 8; k++) {
                int col = ncol0 + (k >> 1) * 8 + 2 * t4 + (k & 1);
                atomicMin(&scol[b0 * TJ + col], __float_as_uint(cmin[k]));
            }
        }
        __syncthreads();   // epilogue reads + scol atomics done; b0 safe for refill

        // per-tile column flush + re-arm
        if (tid < TJ) {
            unsigned v = scol[b0 * TJ + tid];
            if (v != FINF) atomicMin(&g_negmin[j0 + tid], v);
            scol[b0 * TJ + tid] = FINF;
        }

        // [4] i-tile boundary: flush rmin, reload A and row constants (rare)
        if (ichange) {
#pragma unroll
            for (int h = 0; h < 4; h++) {
                rmin[h] = fminf(rmin[h], __shfl_xor_sync(0xffffffffu, rmin[h], 1));
                rmin[h] = fminf(rmin[h], __shfl_xor_sync(0xffffffffu, rmin[h], 2));
            }
            if (t4 == 0) {
#pragma unroll
                for (int mf = 0; mf < 2; mf++)
#pragma unroll
                    for (int hh = 0; hh < 2; hh++)
                        atomicMin(&smin[mrow0 + mf * 16 + hh * 8 + g],
                                  __float_as_uint(rmin[mf * 2 + hh]));
            }
            __syncthreads();
            if (tid < 128) {
                atomicMin(&g_negmin[i0 + tid], smin[tid]);
                smin[tid] = FINF;
            }

            it = it + 1;
            i0 = it * TI;
#pragma unroll
            for (int c = tid; c < 2048; c += NTHREADS) {
                int row = c >> 4, col = c & 15;
                CP_ASYNC16(sb + OFF_A + row * PITCH + col * 16,
                           (const void*)(g_H + (size_t)(i0 + row) * DD + col * 8));
            }
            CP_COMMIT();
            CP_WAIT0();
            __syncthreads();
#pragma unroll
            for (int mf = 0; mf < 2; mf++)
#pragma unroll
                for (int hh = 0; hh < 2; hh++) {
                    int r = mrow0 + mf * 16 + hh * 8 + g;
                    si[mf * 2 + hh] = g_sq[i0 + r];
                    li[mf * 2 + hh] = g_lab32[i0 + r];
                    rmin[mf * 2 + hh] = __int_as_float(FINF);
                }
        }
    }

    // ---- final row flush ----
#pragma unroll
    for (int h = 0; h < 4; h++) {
        rmin[h] = fminf(rmin[h], __shfl_xor_sync(0xffffffffu, rmin[h], 1));
        rmin[h] = fminf(rmin[h], __shfl_xor_sync(0xffffffffu, rmin[h], 2));
    }
    if (t4 == 0) {
#pragma unroll
        for (int mf = 0; mf < 2; mf++)
#pragma unroll
            for (int hh = 0; hh < 2; hh++)
                atomicMin(&smin[mrow0 + mf * 16 + hh * 8 + g],
                          __float_as_uint(rmin[mf * 2 + hh]));
    }
    __syncthreads();
    if (tid < 128) atomicMin(&g_negmin[i0 + tid], smin[tid]);

    // ================= software grid barrier =================
    __threadfence();
    __syncthreads();
    if (tid == 0) {
        atomicAdd(&g_bar1, 1);
        while (*(volatile int*)&g_bar1 < GRIDN) { }
    }
    __syncthreads();

    // ================= phase 2: bucket-based positive evaluation =================
    {
        float* ssum = reinterpret_cast<float*>(smem + OFF_SQJ);
        int*   scnt = reinterpret_cast<int*>(smem + OFF_SQJ + 64);
        if (tid == 0) { *ssum = 0.f; *scnt = 0; }
        __syncthreads();

        const int br0 = (1024 * blk) / GRIDN;
        const int br1 = (1024 * (blk + 1)) / GRIDN;
        float lsum = 0.f;
        int   lcnt = 0;

        for (int b = br0 + w; b < br1; b += 8) {   // warp per bucket
            int cnt = g_bcnt[b];
            if (cnt > BCAP) cnt = BCAP;
            if (cnt < 2) continue;
            int idx_l = 0, lab_l = 0x80000000;
            float sq_l = 0.f; unsigned hn_l = FINF;
            if (lane < cnt) {
                idx_l = g_bmem[b * BCAP + lane];
                lab_l = g_lab32[idx_l];
                sq_l  = g_sq[idx_l];
                hn_l  = g_negmin[idx_l];
            }
            for (int mi = 0; mi < cnt; mi++) {
                unsigned hnb = __shfl_sync(0xffffffffu, hn_l, mi);
                if (hnb == FINF) continue;
                float hn  = __uint_as_float(hnb);
                int   i   = __shfl_sync(0xffffffffu, idx_l, mi);
                int   labi = __shfl_sync(0xffffffffu, lab_l, mi);
                float sqi = __shfl_sync(0xffffffffu, sq_l, mi);
                uint2 ra = *reinterpret_cast<const uint2*>(g_H + (size_t)i * DD + lane * 4);
                float2 af0 = __half22float2(*reinterpret_cast<__half2*>(&ra.x));
                float2 af1 = __half22float2(*reinterpret_cast<__half2*>(&ra.y));
                for (int mj = 0; mj < cnt; mj++) {
                    if (mj == mi) continue;
                    int labj = __shfl_sync(0xffffffffu, lab_l, mj);
                    if (labj != labi) continue;    // guards label-mod-1024 collisions
                    int   j   = __shfl_sync(0xffffffffu, idx_l, mj);
                    float sqjv = __shfl_sync(0xffffffffu, sq_l, mj);
                    uint2 rb = *reinterpret_cast<const uint2*>(g_H + (size_t)j * DD + lane * 4);
                    float2 bf0 = __half22float2(*reinterpret_cast<__half2*>(&rb.x));
                    float2 bf1 = __half22float2(*reinterpret_cast<__half2*>(&rb.y));
                    float dot = af0.x * bf0.x + af0.y * bf0.y + af1.x * bf1.x + af1.y * bf1.y;
#pragma unroll
                    for (int off = 16; off; off >>= 1)
                        dot += __shfl_xor_sync(0xffffffffu, dot, off);
                    float dpos = sqi + sqjv - 2.0f * dot;
                    if (hn < dpos) { lsum += dpos - hn + TMARGIN; lcnt += 1; }
                }
            }
        }
        // lsum/lcnt identical across lanes (all values warp-uniform) -> lane 0 publishes
        if (lane == 0 && lcnt) {
            atomicAdd(ssum, lsum);
            atomicAdd(scnt, lcnt);
        }
        __syncthreads();
        if (tid == 0 && *scnt) {
            atomicAdd(&g_total, *ssum);
            atomicAdd(&g_count, *scnt);
        }
        // re-zero this CTA's bucket counters for the next graph replay
        for (int b = br0 + tid; b < br1; b += NTHREADS) g_bcnt[b] = 0;
    }

    // ================= finalize: last CTA writes output =================
    __threadfence();
    __syncthreads();
    if (tid == 0) {
        int r = atomicAdd(&g_bar2, 1);
        if (r == GRIDN - 1) {
            float c = (float)g_count;
            float loss = g_total / fmaxf(c, 1.f);
            if (out_size >= 1) out[0] = loss;
            if (out_size >= 2) out[1] = c;
        }
    }
}

extern "C" void kernel_launch(void* const* d_in, const int* in_sizes, int n_in,
                              void* d_out, int out_size) {
    const float* E = (const float*)d_in[0];
    const void* lab = d_in[1];
    float* out = (float*)d_out;

    cudaFuncSetAttribute(negmine_kernel, cudaFuncAttributeMaxDynamicSharedMemorySize, SMEM_TOTAL);

    setup_kernel<<<BN / 8, 256>>>(E, lab);
    negmine_kernel<<<GRIDN, NTHREADS, SMEM_TOTAL>>>(out, out_size);
}

// round 15
// speedup vs baseline: 1.9891x; 1.9891x over previous
#include <cuda_runtime.h>
#include <cuda_fp16.h>
#include <cstdint>

// ---------------- problem constants ----------------
#define BN 8192
#define DD 128
#define TMARGIN 1.0f

// ---------------- tiling (round-12 proven geometry) ----------------
#define TI 128
#define TJ 64
// Lower-triangle tile enumeration: for i-tile `it`, j-tiles 0..2it+1.
#define TOTAL_TILES 4160
#define GRIDN 444                  // 148 SMs x 3 CTAs (exactly resident)
#define PITCH 272                  // 256B data + 16B pad -> conflict-free ldmatrix
#define ATILEB (128 * PITCH)       // 34816
#define BTILEB (TJ * PITCH)        // 17408
#define SLAB 2048                  // positive-pair slots per CTA (expected ~260)
#define NTHREADS 256
#define FINF 0x7f800000u

// ---------------- device globals ----------------
__device__ float        g_sq[BN];
__device__ unsigned int g_negmin[BN];
__device__ float        g_total;
__device__ int          g_count;
__device__ int          g_lab32[BN];
__device__ __half       g_H[BN * DD];
__device__ int          g_pi[GRIDN * SLAB];
__device__ float        g_pd[GRIDN * SLAB];
__device__ int          g_bar1;
__device__ int          g_bar2;

// ---------------- PTX helpers (baseline, legal at target sm_103) ----------------
__device__ __forceinline__ uint32_t smem_u32(const void* p) {
    uint32_t a;
    asm("{ .reg .u64 t; cvta.to.shared.u64 t, %1; cvt.u32.u64 %0, t; }" : "=r"(a) : "l"(p));
    return a;
}
#define CP_ASYNC16(dst, src) \
    asm volatile("cp.async.cg.shared.global [%0], [%1], 16;" :: "r"(dst), "l"(src))
#define CP_COMMIT() asm volatile("cp.async.commit_group;")
#define CP_WAIT1()  asm volatile("cp.async.wait_group 1;")
#define CP_WAIT0()  asm volatile("cp.async.wait_group 0;")

#define LDSM_X4(r0, r1, r2, r3, addr) \
    asm volatile("ldmatrix.sync.aligned.m8n8.x4.shared.b16 {%0,%1,%2,%3}, [%4];" \
                 : "=r"(r0), "=r"(r1), "=r"(r2), "=r"(r3) : "r"(addr))

#define MMA16816(d, a0, a1, a2, a3, b0, b1) \
    asm volatile("mma.sync.aligned.m16n8k16.row.col.f32.f16.f16.f32 " \
                 "{%0,%1,%2,%3}, {%4,%5,%6,%7}, {%8,%9}, {%0,%1,%2,%3};" \
                 : "+f"((d)[0]), "+f"((d)[1]), "+f"((d)[2]), "+f"((d)[3]) \
                 : "r"(a0), "r"(a1), "r"(a2), "r"(a3), "r"(b0), "r"(b1))

// ---------------- SMEM layout ----------------
#define OFF_A    0
#define OFF_B    ATILEB                      // 2 buffers of BTILEB
#define OFF_SQJ  (ATILEB + 2 * BTILEB)       // float [2][TJ]
#define OFF_LABJ (OFF_SQJ + 2 * TJ * 4)      // int   [2][TJ]
#define OFF_SMIN (OFF_LABJ + 2 * TJ * 4)     // uint  [128]       (row mins)
#define OFF_CMIN (OFF_SMIN + 512)            // uint  [2][8][32]  (per-warp col mins)
#define OFF_PCNT (OFF_CMIN + 2048)           // int   (positive slab counter)
#define SMEM_TOTAL (OFF_PCNT + 16)           // ~73.2 KB -> 3 CTAs/SM (219.7 KB)

// ---------------- fused setup: label init + fp16 convert + row norms ----------------
__global__ void setup_kernel(const float* __restrict__ E, const void* __restrict__ labraw) {
    __shared__ int s_any;
    if (threadIdx.x == 0) s_any = 0;
    __syncthreads();
    // dtype detection: int64 labels < 1024 => odd 32-bit words of first 128 pairs all 0
    if (threadIdx.x < 128) {
        int v = ((const int*)labraw)[2 * threadIdx.x + 1];
        unsigned any = __ballot_sync(0xffffffffu, v != 0);
        if ((threadIdx.x & 31) == 0 && any) atomicOr(&s_any, 1);
    }

    // one warp per row: convert + squared norm
    const int warp = threadIdx.x >> 5, lane = threadIdx.x & 31;
    const int row = blockIdx.x * 8 + warp;
    const float* r = E + (size_t)row * DD;
    __half* h = g_H + (size_t)row * DD;
    float s = 0.f;
#pragma unroll
    for (int q = 0; q < 4; q++) {
        float v = r[lane + 32 * q];
        h[lane + 32 * q] = __float2half(v);
        s += v * v;
    }
#pragma unroll
    for (int off = 16; off; off >>= 1) s += __shfl_xor_sync(0xffffffffu, s, off);
    if (lane == 0) g_sq[row] = s;

    __syncthreads();
    const int is64 = (s_any == 0);
    if (threadIdx.x < 8) {
        int i = blockIdx.x * 8 + threadIdx.x;
        g_negmin[i] = FINF;
        g_lab32[i] = is64 ? (int)((const long long*)labraw)[i] : ((const int*)labraw)[i];
    }
    if (blockIdx.x == 0 && threadIdx.x == 0) {
        g_total = 0.f; g_count = 0; g_bar1 = 0; g_bar2 = 0;
    }
}

// ---------------- HMMA fused Gram + row/col masked-min + positives + finalize ----------------
__global__ __launch_bounds__(NTHREADS, 3) void negmine_kernel(float* out, int out_size) {
    extern __shared__ char smem[];
    const uint32_t sb = smem_u32(smem);
    const int tid = threadIdx.x;
    const int w = tid >> 5, lane = tid & 31;
    const int g = lane >> 2, t4 = lane & 3;

    const int mrow0 = (w & 3) * 32;
    const int ncol0 = (w >> 2) * 32;

    const int blk = blockIdx.x;
    const int t0 = (TOTAL_TILES * blk) / GRIDN;
    const int t1 = (TOTAL_TILES * (blk + 1)) / GRIDN;
    const int sbase = blk * SLAB;

    float* sqj_all  = reinterpret_cast<float*>(smem + OFF_SQJ);
    int*   labj_all = reinterpret_cast<int*>(smem + OFF_LABJ);
    unsigned* smin  = reinterpret_cast<unsigned*>(smem + OFF_SMIN);
    unsigned* scolf = reinterpret_cast<unsigned*>(smem + OFF_CMIN);  // [2][8][32]
    int* s_pcnt     = reinterpret_cast<int*>(smem + OFF_PCNT);

    // decode i-tile of t0: it*(it+1) <= t0 < (it+1)*(it+2)
    int it = (int)((sqrtf(4.0f * (float)t0 + 1.0f) - 1.0f) * 0.5f);
    while ((it + 1) * (it + 2) <= t0) it++;
    while (it * (it + 1) > t0) it--;
    int i0 = it * TI;

    // ---- prologue: A(it) + B(t0) ----
#pragma unroll
    for (int c = tid; c < 2048; c += NTHREADS) {
        int row = c >> 4, col = c & 15;
        CP_ASYNC16(sb + OFF_A + row * PITCH + col * 16,
                   (const void*)(g_H + (size_t)(i0 + row) * DD + col * 8));
    }
    {
        const int j0 = (t0 - it * (it + 1)) * TJ;
#pragma unroll
        for (int c = tid; c < 1024; c += NTHREADS) {
            int row = c >> 4, col = c & 15;
            CP_ASYNC16(sb + OFF_B + row * PITCH + col * 16,
                       (const void*)(g_H + (size_t)(j0 + row) * DD + col * 8));
        }
        CP_COMMIT();
        if (tid < TJ) {
            sqj_all[tid]  = g_sq[j0 + tid];
            labj_all[tid] = g_lab32[j0 + tid];
        }
    }
    if (tid < 128) smin[tid] = FINF;
    for (int e = tid; e < 512; e += NTHREADS) scolf[e] = FINF;
    if (tid == 0) *s_pcnt = 0;
    CP_WAIT0();
    __syncthreads();

    // ---- per-lane ldmatrix bases ----
    uint32_t abase[2];
#pragma unroll
    for (int mf = 0; mf < 2; mf++)
        abase[mf] = sb + OFF_A
                  + (uint32_t)((mrow0 + mf * 16 + ((lane >> 3) & 1) * 8 + (lane & 7)) * PITCH)
                  + (uint32_t)((lane >> 4) * 16);
    uint32_t bbase[2];
#pragma unroll
    for (int p = 0; p < 2; p++)
        bbase[p] = sb + OFF_B
                 + (uint32_t)((ncol0 + p * 16 + ((lane >> 4) & 1) * 8 + (lane & 7)) * PITCH)
                 + (uint32_t)(((lane >> 3) & 1) * 16);

    // ---- per-i row constants ----
    float si[4]; int li[4];
#pragma unroll
    for (int mf = 0; mf < 2; mf++)
#pragma unroll
        for (int hh = 0; hh < 2; hh++) {
            int r = mrow0 + mf * 16 + hh * 8 + g;
            si[mf * 2 + hh] = g_sq[i0 + r];
            li[mf * 2 + hh] = g_lab32[i0 + r];
        }
    float rmin[4];
#pragma unroll
    for (int h = 0; h < 4; h++) rmin[h] = __int_as_float(FINF);

    // ---- phase 1: persistent mining loop ----
    for (int t = t0; t < t1; t++) {
        const int b0 = (t - t0) & 1;
        const int jt = t - it * (it + 1);
        const int j0 = jt * TJ;
        const bool do_col = (jt < 2 * it);
        const bool last = (t + 1 == t1);
        const bool ichange = !last && (t + 1 == (it + 1) * (it + 2));

        // [1] prefetch next B
        if (!last) {
            const int b1 = b0 ^ 1;
            const int itn = ichange ? it + 1 : it;
            const int j1 = ((t + 1) - itn * (itn + 1)) * TJ;
#pragma unroll
            for (int c = tid; c < 1024; c += NTHREADS) {
                int row = c >> 4, col = c & 15;
                CP_ASYNC16(sb + OFF_B + b1 * BTILEB + row * PITCH + col * 16,
                           (const void*)(g_H + (size_t)(j1 + row) * DD + col * 8));
            }
            CP_COMMIT();
            if (tid < TJ) {
                sqj_all[b1 * TJ + tid]  = g_sq[j1 + tid];
                labj_all[b1 * TJ + tid] = g_lab32[j1 + tid];
            }
            CP_WAIT1();
        } else {
            CP_WAIT0();
        }
        __syncthreads();   // B(t) visible to all; prefetch writes published

        // [2] compute: 8 k-steps x (2A + 2B LDSM, 8 MMA)
        float acc[2][4][4];
#pragma unroll
        for (int mf = 0; mf < 2; mf++)
#pragma unroll
            for (int nf = 0; nf < 4; nf++)
#pragma unroll
                for (int e = 0; e < 4; e++) acc[mf][nf][e] = 0.f;

        const uint32_t bufoff = (uint32_t)(b0 * BTILEB);
#pragma unroll
        for (int ks = 0; ks < DD / 16; ks++) {
            uint32_t a0[4], a1[4], bf[2][4];
            LDSM_X4(a0[0], a0[1], a0[2], a0[3], abase[0] + ks * 32);
            LDSM_X4(a1[0], a1[1], a1[2], a1[3], abase[1] + ks * 32);
            LDSM_X4(bf[0][0], bf[0][1], bf[0][2], bf[0][3], bbase[0] + bufoff + ks * 32);
            LDSM_X4(bf[1][0], bf[1][1], bf[1][2], bf[1][3], bbase[1] + bufoff + ks * 32);
#pragma unroll
            for (int nf = 0; nf < 4; nf++) {
                MMA16816(acc[0][nf], a0[0], a0[1], a0[2], a0[3],
                         bf[nf >> 1][(nf & 1) * 2], bf[nf >> 1][(nf & 1) * 2 + 1]);
                MMA16816(acc[1][nf], a1[0], a1[1], a1[2], a1[3],
                         bf[nf >> 1][(nf & 1) * 2], bf[nf >> 1][(nf & 1) * 2 + 1]);
            }
        }

        // [3] epilogue: branch-free masked mins + ballot-guarded rare emission
        const float2* sqj2  = reinterpret_cast<const float2*>(sqj_all + b0 * TJ);
        const int2*   labj2 = reinterpret_cast<const int2*>(labj_all + b0 * TJ);
        const float INF = __int_as_float(FINF);
        float cmin[8];
#pragma unroll
        for (int k = 0; k < 8; k++) cmin[k] = INF;

#pragma unroll
        for (int nf = 0; nf < 4; nf++) {
            const int c0 = ncol0 + nf * 8 + 2 * t4;
            const float2 q = sqj2[c0 >> 1];
            const int2  lb = labj2[c0 >> 1];
            unsigned pm = 0;
#pragma unroll
            for (int mf = 0; mf < 2; mf++)
#pragma unroll
                for (int hh = 0; hh < 2; hh++) {
                    const int ri = mf * 2 + hh;
                    float dd0 = fmaf(acc[mf][nf][hh * 2 + 0], -2.0f, si[ri] + q.x);
                    float dd1 = fmaf(acc[mf][nf][hh * 2 + 1], -2.0f, si[ri] + q.y);
                    bool p0 = (lb.x == li[ri]);
                    bool p1 = (lb.y == li[ri]);
                    float v0 = p0 ? INF : dd0;
                    float v1 = p1 ? INF : dd1;
                    rmin[ri] = fminf(rmin[ri], fminf(v0, v1));
                    cmin[nf * 2]     = fminf(cmin[nf * 2], v0);
                    cmin[nf * 2 + 1] = fminf(cmin[nf * 2 + 1], v1);
                    pm |= (p0 ? (1u << (ri * 2)) : 0u) | (p1 ? (1u << (ri * 2 + 1)) : 0u);
                }
            // rare path: any positive pair in this warp's nf-group?
            if (__ballot_sync(0xffffffffu, pm != 0)) {
                if (pm) {
#pragma unroll
                    for (int mf = 0; mf < 2; mf++)
#pragma unroll
                        for (int hh = 0; hh < 2; hh++) {
                            const int ri = mf * 2 + hh;
                            const int irow = i0 + mrow0 + mf * 16 + hh * 8 + g;
                            if (pm & (1u << (ri * 2))) {
                                float dd0 = fmaf(acc[mf][nf][hh * 2 + 0], -2.0f, si[ri] + q.x);
                                if (j0 + c0 != irow) {
                                    int slot = atomicAdd(s_pcnt, 1);
                                    if (slot < SLAB) { g_pi[sbase + slot] = irow; g_pd[sbase + slot] = dd0; }
                                }
                                if (do_col) {
                                    int slot = atomicAdd(s_pcnt, 1);
                                    if (slot < SLAB) { g_pi[sbase + slot] = j0 + c0; g_pd[sbase + slot] = dd0; }
                                }
                            }
                            if (pm & (1u << (ri * 2 + 1))) {
                                float dd1 = fmaf(acc[mf][nf][hh * 2 + 1], -2.0f, si[ri] + q.y);
                                if (j0 + c0 + 1 != irow) {
                                    int slot = atomicAdd(s_pcnt, 1);
                                    if (slot < SLAB) { g_pi[sbase + slot] = irow; g_pd[sbase + slot] = dd1; }
                                }
                                if (do_col) {
                                    int slot = atomicAdd(s_pcnt, 1);
                                    if (slot < SLAB) { g_pi[sbase + slot] = j0 + c0 + 1; g_pd[sbase + slot] = dd1; }
                                }
                            }
                        }
                }
            }
        }

        // column reduce across the 8 g-lanes sharing each column
#pragma unroll
        for (int k = 0; k < 8; k++) {
            float v = cmin[k];
            v = fminf(v, __shfl_xor_sync(0xffffffffu, v, 4));
            v = fminf(v, __shfl_xor_sync(0xffffffffu, v, 8));
            v = fminf(v, __shfl_xor_sync(0xffffffffu, v, 16));
            cmin[k] = v;
        }
        // private per-warp column mins: plain stores, no atomics
        if (lane < 4) {
            unsigned* myscol = scolf + b0 * 256 + w * 32;
#pragma unroll
            for (int k = 0; k < 8; k++) {
                int cl = (k >> 1) * 8 + 2 * t4 + (k & 1);
                myscol[cl] = __float_as_uint(cmin[k]);
            }
        }
        __syncthreads();   // epilogue reads + scol stores done; b0 safe for refill

        // per-tile column flush: reduce the 4 owning-warp copies, then re-arm (same threads)
        if (tid < TJ) {
            const int grp = (tid >> 5) * 4;   // warps owning this column group
            const int cl = tid & 31;
            unsigned v = FINF;
#pragma unroll
            for (int r = 0; r < 4; r++) {
                unsigned* p = &scolf[b0 * 256 + (grp + r) * 32 + cl];
                unsigned x = *p;
                *p = FINF;
                v = x < v ? x : v;
            }
            if (v != FINF) atomicMin(&g_negmin[j0 + tid], v);
        }

        // [4] i-tile boundary: flush rmin, reload A and row constants (rare)
        if (ichange) {
#pragma unroll
            for (int h = 0; h < 4; h++) {
                rmin[h] = fminf(rmin[h], __shfl_xor_sync(0xffffffffu, rmin[h], 1));
                rmin[h] = fminf(rmin[h], __shfl_xor_sync(0xffffffffu, rmin[h], 2));
            }
            if (t4 == 0) {
#pragma unroll
                for (int mf = 0; mf < 2; mf++)
#pragma unroll
                    for (int hh = 0; hh < 2; hh++)
                        atomicMin(&smin[mrow0 + mf * 16 + hh * 8 + g],
                                  __float_as_uint(rmin[mf * 2 + hh]));
            }
            __syncthreads();
            if (tid < 128) {
                atomicMin(&g_negmin[i0 + tid], smin[tid]);
                smin[tid] = FINF;
            }

            it = it + 1;
            i0 = it * TI;
#pragma unroll
            for (int c = tid; c < 2048; c += NTHREADS) {
                int row = c >> 4, col = c & 15;
                CP_ASYNC16(sb + OFF_A + row * PITCH + col * 16,
                           (const void*)(g_H + (size_t)(i0 + row) * DD + col * 8));
            }
            CP_COMMIT();
            CP_WAIT0();
            __syncthreads();
#pragma unroll
            for (int mf = 0; mf < 2; mf++)
#pragma unroll
                for (int hh = 0; hh < 2; hh++) {
                    int r = mrow0 + mf * 16 + hh * 8 + g;
                    si[mf * 2 + hh] = g_sq[i0 + r];
                    li[mf * 2 + hh] = g_lab32[i0 + r];
                    rmin[mf * 2 + hh] = __int_as_float(FINF);
                }
        }
    }

    // ---- final row flush ----
#pragma unroll
    for (int h = 0; h < 4; h++) {
        rmin[h] = fminf(rmin[h], __shfl_xor_sync(0xffffffffu, rmin[h], 1));
        rmin[h] = fminf(rmin[h], __shfl_xor_sync(0xffffffffu, rmin[h], 2));
    }
    if (t4 == 0) {
#pragma unroll
        for (int mf = 0; mf < 2; mf++)
#pragma unroll
            for (int hh = 0; hh < 2; hh++)
                atomicMin(&smin[mrow0 + mf * 16 + hh * 8 + g],
                          __float_as_uint(rmin[mf * 2 + hh]));
    }
    __syncthreads();
    if (tid < 128) atomicMin(&g_negmin[i0 + tid], smin[tid]);

    // ================= software grid barrier =================
    __threadfence();
    __syncthreads();
    if (tid == 0) {
        atomicAdd(&g_bar1, 1);
        while (*(volatile int*)&g_bar1 < GRIDN) { }
    }
    __syncthreads();

    // ================= phase 2: own-slab positive evaluation =================
    {
        float* ssum = reinterpret_cast<float*>(smem + OFF_SQJ);
        int*   scnt = reinterpret_cast<int*>(smem + OFF_SQJ + 64);
        if (tid == 0) { *ssum = 0.f; *scnt = 0; }
        __syncthreads();

        const int n = min(*s_pcnt, SLAB);
        float lsum = 0.f;
        int   lcnt = 0;
        for (int idx = tid; idx < n; idx += NTHREADS) {
            int i = g_pi[sbase + idx];
            unsigned nb = g_negmin[i];
            if (nb != FINF) {
                float hn = __uint_as_float(nb);
                float dpos = g_pd[sbase + idx];
                if (hn < dpos) { lsum += dpos - hn + TMARGIN; lcnt += 1; }
            }
        }
#pragma unroll
        for (int off = 16; off; off >>= 1) {
            lsum += __shfl_xor_sync(0xffffffffu, lsum, off);
            lcnt += __shfl_xor_sync(0xffffffffu, lcnt, off);
        }
        if (lane == 0 && lcnt) {
            atomicAdd(ssum, lsum);
            atomicAdd(scnt, lcnt);
        }
        __syncthreads();
        if (tid == 0 && *scnt) {
            atomicAdd(&g_total, *ssum);
            atomicAdd(&g_count, *scnt);
        }
    }

    // ================= finalize: last CTA writes output =================
    __threadfence();
    __syncthreads();
    if (tid == 0) {
        int r = atomicAdd(&g_bar2, 1);
        if (r == GRIDN - 1) {
            float c = (float)g_count;
            float loss = g_total / fmaxf(c, 1.f);
            if (out_size >= 1) out[0] = loss;
            if (out_size >= 2) out[1] = c;
        }
    }
}

extern "C" void kernel_launch(void* const* d_in, const int* in_sizes, int n_in,
                              void* d_out, int out_size) {
    const float* E = (const float*)d_in[0];
    const void* lab = d_in[1];
    float* out = (float*)d_out;

    cudaFuncSetAttribute(negmine_kernel, cudaFuncAttributeMaxDynamicSharedMemorySize, SMEM_TOTAL);

    setup_kernel<<<BN / 8, 256>>>(E, lab);
    negmine_kernel<<<GRIDN, NTHREADS, SMEM_TOTAL>>>(out, out_size);
}

// round 16
// speedup vs baseline: 2.0040x; 1.0075x over previous
#include <cuda_runtime.h>
#include <cuda_fp16.h>
#include <cstdint>

// ---------------- problem constants ----------------
#define BN 8192
#define DD 128
#define TMARGIN 1.0f

// ---------------- tiling (round-12 proven geometry) ----------------
#define TI 128
#define TJ 64
// Lower-triangle tile enumeration: for i-tile `it`, j-tiles 0..2it+1.
#define TOTAL_TILES 4160
#define GRIDN 444                  // 148 SMs x 3 CTAs (exactly resident)
#define PITCH 272                  // 256B data + 16B pad -> conflict-free ldmatrix
#define ATILEB (128 * PITCH)       // 34816
#define BTILEB (TJ * PITCH)        // 17408
#define SLAB 2048                  // positive-pair slots per CTA (expected ~260)
#define NTHREADS 256
#define FINF 0x7f800000u

// ---------------- device globals ----------------
__device__ float        g_sq[BN];
__device__ unsigned int g_negmin[BN];
__device__ float        g_total;
__device__ int          g_count;
__device__ int          g_lab32[BN];
__device__ __half       g_H[BN * DD];
__device__ int          g_pi[GRIDN * SLAB];
__device__ float        g_pd[GRIDN * SLAB];
__device__ int          g_bar1;
__device__ int          g_bar2;

// ---------------- PTX helpers (baseline, legal at target sm_103) ----------------
__device__ __forceinline__ uint32_t smem_u32(const void* p) {
    uint32_t a;
    asm("{ .reg .u64 t; cvta.to.shared.u64 t, %1; cvt.u32.u64 %0, t; }" : "=r"(a) : "l"(p));
    return a;
}
#define CP_ASYNC16(dst, src) \
    asm volatile("cp.async.cg.shared.global [%0], [%1], 16;" :: "r"(dst), "l"(src))
#define CP_COMMIT() asm volatile("cp.async.commit_group;")
#define CP_WAIT1()  asm volatile("cp.async.wait_group 1;")
#define CP_WAIT0()  asm volatile("cp.async.wait_group 0;")

#define LDSM_X4(r0, r1, r2, r3, addr) \
    asm volatile("ldmatrix.sync.aligned.m8n8.x4.shared.b16 {%0,%1,%2,%3}, [%4];" \
                 : "=r"(r0), "=r"(r1), "=r"(r2), "=r"(r3) : "r"(addr))

#define MMA16816(d, a0, a1, a2, a3, b0, b1) \
    asm volatile("mma.sync.aligned.m16n8k16.row.col.f32.f16.f16.f32 " \
                 "{%0,%1,%2,%3}, {%4,%5,%6,%7}, {%8,%9}, {%0,%1,%2,%3};" \
                 : "+f"((d)[0]), "+f"((d)[1]), "+f"((d)[2]), "+f"((d)[3]) \
                 : "r"(a0), "r"(a1), "r"(a2), "r"(a3), "r"(b0), "r"(b1))

// ---------------- SMEM layout ----------------
#define OFF_A     0
#define OFF_B     ATILEB                     // 2 buffers of BTILEB (ends 69632)
#define OFF_SQLAB (ATILEB + 2 * BTILEB)      // int4 [2][32]: {sq0,sq1,lab0,lab1}
#define OFF_SMIN  (OFF_SQLAB + 1024)         // uint [128]      (row mins)
#define OFF_CMIN  (OFF_SMIN + 512)           // uint [2][8][32] (per-warp col mins)
#define OFF_PCNT  (OFF_CMIN + 2048)          // int  (positive slab counter)
#define SMEM_TOTAL (OFF_PCNT + 16)           // 73232 B -> 3 CTAs/SM (219.7 KB)

// ---------------- fused setup: label init + fp16 convert + row norms ----------------
__global__ void setup_kernel(const float* __restrict__ E, const void* __restrict__ labraw) {
    __shared__ int s_any;
    if (threadIdx.x == 0) s_any = 0;
    __syncthreads();
    // dtype detection: int64 labels < 1024 => odd 32-bit words of first 128 pairs all 0
    if (threadIdx.x < 128) {
        int v = ((const int*)labraw)[2 * threadIdx.x + 1];
        unsigned any = __ballot_sync(0xffffffffu, v != 0);
        if ((threadIdx.x & 31) == 0 && any) atomicOr(&s_any, 1);
    }

    // one warp per row: convert + squared norm
    const int warp = threadIdx.x >> 5, lane = threadIdx.x & 31;
    const int row = blockIdx.x * 8 + warp;
    const float* r = E + (size_t)row * DD;
    __half* h = g_H + (size_t)row * DD;
    float s = 0.f;
#pragma unroll
    for (int q = 0; q < 4; q++) {
        float v = r[lane + 32 * q];
        h[lane + 32 * q] = __float2half(v);
        s += v * v;
    }
#pragma unroll
    for (int off = 16; off; off >>= 1) s += __shfl_xor_sync(0xffffffffu, s, off);
    if (lane == 0) g_sq[row] = s;

    __syncthreads();
    const int is64 = (s_any == 0);
    if (threadIdx.x < 8) {
        int i = blockIdx.x * 8 + threadIdx.x;
        g_negmin[i] = FINF;
        g_lab32[i] = is64 ? (int)((const long long*)labraw)[i] : ((const int*)labraw)[i];
    }
    if (blockIdx.x == 0 && threadIdx.x == 0) {
        g_total = 0.f; g_count = 0; g_bar1 = 0; g_bar2 = 0;
    }
}

// ---------------- HMMA fused Gram + row/col masked-min + positives + finalize ----------------
__global__ __launch_bounds__(NTHREADS, 3) void negmine_kernel(float* out, int out_size) {
    extern __shared__ char smem[];
    const uint32_t sb = smem_u32(smem);
    const int tid = threadIdx.x;
    const int w = tid >> 5, lane = tid & 31;
    const int g = lane >> 2, t4 = lane & 3;

    const int mrow0 = (w & 3) * 32;
    const int ncol0 = (w >> 2) * 32;

    const int blk = blockIdx.x;
    const int t0 = (TOTAL_TILES * blk) / GRIDN;
    const int t1 = (TOTAL_TILES * (blk + 1)) / GRIDN;
    const int sbase = blk * SLAB;

    int4* sqlab     = reinterpret_cast<int4*>(smem + OFF_SQLAB);      // [2][32]
    unsigned* smin  = reinterpret_cast<unsigned*>(smem + OFF_SMIN);
    unsigned* scolf = reinterpret_cast<unsigned*>(smem + OFF_CMIN);   // [2][8][32]
    int* s_pcnt     = reinterpret_cast<int*>(smem + OFF_PCNT);

    // ---- precomputed per-thread copy-loop addressing ----
    const int arow  = tid >> 4;            // base row within tile (chunks stride +16 rows)
    const int acol8 = (tid & 15) * 8;      // element column offset (16B chunks)
    const uint32_t dstA = sb + OFF_A + (uint32_t)(arow * PITCH + (tid & 15) * 16);
    const uint32_t dstB = sb + OFF_B + (uint32_t)(arow * PITCH + (tid & 15) * 16);

    // decode i-tile of t0: it*(it+1) <= t0 < (it+1)*(it+2)
    int it = (int)((sqrtf(4.0f * (float)t0 + 1.0f) - 1.0f) * 0.5f);
    while ((it + 1) * (it + 2) <= t0) it++;
    while (it * (it + 1) > t0) it--;
    int i0 = it * TI;

    // ---- prologue: A(it) + B(t0) ----
    {
        const __half* asrc = g_H + (size_t)(i0 + arow) * DD + acol8;
#pragma unroll
        for (int k = 0; k < 8; k++)
            CP_ASYNC16(dstA + k * (16 * PITCH), asrc + k * (16 * DD));
        const int j0 = (t0 - it * (it + 1)) * TJ;
        const __half* bsrc = g_H + (size_t)(j0 + arow) * DD + acol8;
#pragma unroll
        for (int k = 0; k < 4; k++)
            CP_ASYNC16(dstB + k * (16 * PITCH), bsrc + k * (16 * DD));
        CP_COMMIT();
        if (tid < 32) {
            int j = j0 + 2 * tid;
            float2 s2 = *reinterpret_cast<const float2*>(g_sq + j);
            int2   l2 = *reinterpret_cast<const int2*>(g_lab32 + j);
            sqlab[tid] = make_int4(__float_as_int(s2.x), __float_as_int(s2.y), l2.x, l2.y);
        }
    }
    if (tid < 128) smin[tid] = FINF;
    for (int e = tid; e < 512; e += NTHREADS) scolf[e] = FINF;
    if (tid == 0) *s_pcnt = 0;
    CP_WAIT0();
    __syncthreads();

    // ---- per-lane ldmatrix bases ----
    uint32_t abase[2];
#pragma unroll
    for (int mf = 0; mf < 2; mf++)
        abase[mf] = sb + OFF_A
                  + (uint32_t)((mrow0 + mf * 16 + ((lane >> 3) & 1) * 8 + (lane & 7)) * PITCH)
                  + (uint32_t)((lane >> 4) * 16);
    uint32_t bbase[2];
#pragma unroll
    for (int p = 0; p < 2; p++)
        bbase[p] = sb + OFF_B
                 + (uint32_t)((ncol0 + p * 16 + ((lane >> 4) & 1) * 8 + (lane & 7)) * PITCH)
                 + (uint32_t)(((lane >> 3) & 1) * 16);

    // ---- per-i row constants ----
    float si[4]; int li[4];
#pragma unroll
    for (int mf = 0; mf < 2; mf++)
#pragma unroll
        for (int hh = 0; hh < 2; hh++) {
            int r = mrow0 + mf * 16 + hh * 8 + g;
            si[mf * 2 + hh] = g_sq[i0 + r];
            li[mf * 2 + hh] = g_lab32[i0 + r];
        }
    float rmin[4];
#pragma unroll
    for (int h = 0; h < 4; h++) rmin[h] = __int_as_float(FINF);

    // ---- phase 1: persistent mining loop ----
    for (int t = t0; t < t1; t++) {
        const int b0 = (t - t0) & 1;
        const int jt = t - it * (it + 1);
        const int j0 = jt * TJ;
        const bool do_col = (jt < 2 * it);
        const bool last = (t + 1 == t1);
        const bool ichange = !last && (t + 1 == (it + 1) * (it + 2));

        // [1] prefetch next B (precomputed addressing)
        if (!last) {
            const int b1 = b0 ^ 1;
            const int itn = ichange ? it + 1 : it;
            const int j1 = ((t + 1) - itn * (itn + 1)) * TJ;
            const __half* bsrc = g_H + (size_t)(j1 + arow) * DD + acol8;
            const uint32_t bd = dstB + (uint32_t)(b1 * BTILEB);
#pragma unroll
            for (int k = 0; k < 4; k++)
                CP_ASYNC16(bd + k * (16 * PITCH), bsrc + k * (16 * DD));
            CP_COMMIT();
            if (tid < 32) {
                int j = j1 + 2 * tid;
                float2 s2 = *reinterpret_cast<const float2*>(g_sq + j);
                int2   l2 = *reinterpret_cast<const int2*>(g_lab32 + j);
                sqlab[b1 * 32 + tid] = make_int4(__float_as_int(s2.x), __float_as_int(s2.y), l2.x, l2.y);
            }
            CP_WAIT1();
        } else {
            CP_WAIT0();
        }
        __syncthreads();   // B(t) visible to all; prefetch writes published

        // [2] compute: 8 k-steps x (2A + 2B LDSM, 8 MMA)
        float acc[2][4][4];
#pragma unroll
        for (int mf = 0; mf < 2; mf++)
#pragma unroll
            for (int nf = 0; nf < 4; nf++)
#pragma unroll
                for (int e = 0; e < 4; e++) acc[mf][nf][e] = 0.f;

        const uint32_t bufoff = (uint32_t)(b0 * BTILEB);
#pragma unroll
        for (int ks = 0; ks < DD / 16; ks++) {
            uint32_t a0[4], a1[4], bf[2][4];
            LDSM_X4(a0[0], a0[1], a0[2], a0[3], abase[0] + ks * 32);
            LDSM_X4(a1[0], a1[1], a1[2], a1[3], abase[1] + ks * 32);
            LDSM_X4(bf[0][0], bf[0][1], bf[0][2], bf[0][3], bbase[0] + bufoff + ks * 32);
            LDSM_X4(bf[1][0], bf[1][1], bf[1][2], bf[1][3], bbase[1] + bufoff + ks * 32);
#pragma unroll
            for (int nf = 0; nf < 4; nf++) {
                MMA16816(acc[0][nf], a0[0], a0[1], a0[2], a0[3],
                         bf[nf >> 1][(nf & 1) * 2], bf[nf >> 1][(nf & 1) * 2 + 1]);
                MMA16816(acc[1][nf], a1[0], a1[1], a1[2], a1[3],
                         bf[nf >> 1][(nf & 1) * 2], bf[nf >> 1][(nf & 1) * 2 + 1]);
            }
        }

        // [3] epilogue: branch-free masked mins; rare recompute-in-ballot emission
        const int4* sqlab_b = sqlab + b0 * 32;
        const float INF = __int_as_float(FINF);
        float cmin[8];
#pragma unroll
        for (int k = 0; k < 8; k++) cmin[k] = INF;

#pragma unroll
        for (int nf = 0; nf < 4; nf++) {
            const int c0 = ncol0 + nf * 8 + 2 * t4;
            const int4 e = sqlab_b[c0 >> 1];
            const float qx = __int_as_float(e.x), qy = __int_as_float(e.y);
            const int lbx = e.z, lby = e.w;
            bool anyp = false;
#pragma unroll
            for (int mf = 0; mf < 2; mf++)
#pragma unroll
                for (int hh = 0; hh < 2; hh++) {
                    const int ri = mf * 2 + hh;
                    float dd0 = fmaf(acc[mf][nf][hh * 2 + 0], -2.0f, si[ri] + qx);
                    float dd1 = fmaf(acc[mf][nf][hh * 2 + 1], -2.0f, si[ri] + qy);
                    bool p0 = (lbx == li[ri]);
                    bool p1 = (lby == li[ri]);
                    anyp = anyp | p0 | p1;
                    float v0 = p0 ? INF : dd0;
                    float v1 = p1 ? INF : dd1;
                    rmin[ri] = fminf(rmin[ri], fminf(v0, v1));
                    cmin[nf * 2]     = fminf(cmin[nf * 2], v0);
                    cmin[nf * 2 + 1] = fminf(cmin[nf * 2 + 1], v1);
                }
            // rare path: recompute with compile-time indices (no mask encoding)
            if (__ballot_sync(0xffffffffu, anyp)) {
                if (anyp) {
#pragma unroll
                    for (int mf = 0; mf < 2; mf++)
#pragma unroll
                        for (int hh = 0; hh < 2; hh++) {
                            const int ri = mf * 2 + hh;
                            const int irow = i0 + mrow0 + mf * 16 + hh * 8 + g;
                            if (lbx == li[ri]) {
                                float dd0 = fmaf(acc[mf][nf][hh * 2 + 0], -2.0f, si[ri] + qx);
                                if (j0 + c0 != irow) {
                                    int slot = atomicAdd(s_pcnt, 1);
                                    if (slot < SLAB) { g_pi[sbase + slot] = irow; g_pd[sbase + slot] = dd0; }
                                }
                                if (do_col) {
                                    int slot = atomicAdd(s_pcnt, 1);
                                    if (slot < SLAB) { g_pi[sbase + slot] = j0 + c0; g_pd[sbase + slot] = dd0; }
                                }
                            }
                            if (lby == li[ri]) {
                                float dd1 = fmaf(acc[mf][nf][hh * 2 + 1], -2.0f, si[ri] + qy);
                                if (j0 + c0 + 1 != irow) {
                                    int slot = atomicAdd(s_pcnt, 1);
                                    if (slot < SLAB) { g_pi[sbase + slot] = irow; g_pd[sbase + slot] = dd1; }
                                }
                                if (do_col) {
                                    int slot = atomicAdd(s_pcnt, 1);
                                    if (slot < SLAB) { g_pi[sbase + slot] = j0 + c0 + 1; g_pd[sbase + slot] = dd1; }
                                }
                            }
                        }
                }
            }
        }

        // column reduce across the 8 g-lanes sharing each column
#pragma unroll
        for (int k = 0; k < 8; k++) {
            float v = cmin[k];
            v = fminf(v, __shfl_xor_sync(0xffffffffu, v, 4));
            v = fminf(v, __shfl_xor_sync(0xffffffffu, v, 8));
            v = fminf(v, __shfl_xor_sync(0xffffffffu, v, 16));
            cmin[k] = v;
        }
        // private per-warp column mins: plain stores, no atomics
        if (lane < 4) {
            unsigned* myscol = scolf + b0 * 256 + w * 32;
#pragma unroll
            for (int k = 0; k < 8; k++) {
                int cl = (k >> 1) * 8 + 2 * t4 + (k & 1);
                myscol[cl] = __float_as_uint(cmin[k]);
            }
        }
        __syncthreads();   // epilogue reads + scol stores done; b0 safe for refill

        // per-tile column flush: reduce the 4 owning-warp copies, then re-arm
        if (tid < TJ) {
            const int grp = (tid >> 5) * 4;
            const int cl = tid & 31;
            unsigned v = FINF;
#pragma unroll
            for (int r = 0; r < 4; r++) {
                unsigned* p = &scolf[b0 * 256 + (grp + r) * 32 + cl];
                unsigned x = *p;
                *p = FINF;
                v = x < v ? x : v;
            }
            if (v != FINF) atomicMin(&g_negmin[j0 + tid], v);
        }

        // [4] i-tile boundary: flush rmin, reload A and row constants (rare)
        if (ichange) {
#pragma unroll
            for (int h = 0; h < 4; h++) {
                rmin[h] = fminf(rmin[h], __shfl_xor_sync(0xffffffffu, rmin[h], 1));
                rmin[h] = fminf(rmin[h], __shfl_xor_sync(0xffffffffu, rmin[h], 2));
            }
            if (t4 == 0) {
#pragma unroll
                for (int mf = 0; mf < 2; mf++)
#pragma unroll
                    for (int hh = 0; hh < 2; hh++)
                        atomicMin(&smin[mrow0 + mf * 16 + hh * 8 + g],
                                  __float_as_uint(rmin[mf * 2 + hh]));
            }
            __syncthreads();
            if (tid < 128) {
                atomicMin(&g_negmin[i0 + tid], smin[tid]);
                smin[tid] = FINF;
            }

            it = it + 1;
            i0 = it * TI;
            const __half* asrc = g_H + (size_t)(i0 + arow) * DD + acol8;
#pragma unroll
            for (int k = 0; k < 8; k++)
                CP_ASYNC16(dstA + k * (16 * PITCH), asrc + k * (16 * DD));
            CP_COMMIT();
            CP_WAIT0();
            __syncthreads();
#pragma unroll
            for (int mf = 0; mf < 2; mf++)
#pragma unroll
                for (int hh = 0; hh < 2; hh++) {
                    int r = mrow0 + mf * 16 + hh * 8 + g;
                    si[mf * 2 + hh] = g_sq[i0 + r];
                    li[mf * 2 + hh] = g_lab32[i0 + r];
                    rmin[mf * 2 + hh] = __int_as_float(FINF);
                }
        }
    }

    // ---- final row flush ----
#pragma unroll
    for (int h = 0; h < 4; h++) {
        rmin[h] = fminf(rmin[h], __shfl_xor_sync(0xffffffffu, rmin[h], 1));
        rmin[h] = fminf(rmin[h], __shfl_xor_sync(0xffffffffu, rmin[h], 2));
    }
    if (t4 == 0) {
#pragma unroll
        for (int mf = 0; mf < 2; mf++)
#pragma unroll
            for (int hh = 0; hh < 2; hh++)
                atomicMin(&smin[mrow0 + mf * 16 + hh * 8 + g],
                          __float_as_uint(rmin[mf * 2 + hh]));
    }
    __syncthreads();
    if (tid < 128) atomicMin(&g_negmin[i0 + tid], smin[tid]);

    // ================= software grid barrier =================
    __threadfence();
    __syncthreads();
    if (tid == 0) {
        atomicAdd(&g_bar1, 1);
        while (*(volatile int*)&g_bar1 < GRIDN) { }
    }
    __syncthreads();

    // ================= phase 2: own-slab positive evaluation =================
    {
        float* ssum = reinterpret_cast<float*>(smem + OFF_SQLAB);
        int*   scnt = reinterpret_cast<int*>(smem + OFF_SQLAB + 64);
        if (tid == 0) { *ssum = 0.f; *scnt = 0; }
        __syncthreads();

        const int n = min(*s_pcnt, SLAB);
        float lsum = 0.f;
        int   lcnt = 0;
        for (int idx = tid; idx < n; idx += NTHREADS) {
            int i = g_pi[sbase + idx];
            unsigned nb = g_negmin[i];
            if (nb != FINF) {
                float hn = __uint_as_float(nb);
                float dpos = g_pd[sbase + idx];
                if (hn < dpos) { lsum += dpos - hn + TMARGIN; lcnt += 1; }
            }
        }
#pragma unroll
        for (int off = 16; off; off >>= 1) {
            lsum += __shfl_xor_sync(0xffffffffu, lsum, off);
            lcnt += __shfl_xor_sync(0xffffffffu, lcnt, off);
        }
        if (lane == 0 && lcnt) {
            atomicAdd(ssum, lsum);
            atomicAdd(scnt, lcnt);
        }
        __syncthreads();
        if (tid == 0 && *scnt) {
            atomicAdd(&g_total, *ssum);
            atomicAdd(&g_count, *scnt);
        }
    }

    // ================= finalize: last CTA writes output =================
    __threadfence();
    __syncthreads();
    if (tid == 0) {
        int r = atomicAdd(&g_bar2, 1);
        if (r == GRIDN - 1) {
            float c = (float)g_count;
            float loss = g_total / fmaxf(c, 1.f);
            if (out_size >= 1) out[0] = loss;
            if (out_size >= 2) out[1] = c;
        }
    }
}

extern "C" void kernel_launch(void* const* d_in, const int* in_sizes, int n_in,
                              void* d_out, int out_size) {
    const float* E = (const float*)d_in[0];
    const void* lab = d_in[1];
    float* out = (float*)d_out;

    cudaFuncSetAttribute(negmine_kernel, cudaFuncAttributeMaxDynamicSharedMemorySize, SMEM_TOTAL);

    setup_kernel<<<BN / 8, 256>>>(E, lab);
    negmine_kernel<<<GRIDN, NTHREADS, SMEM_TOTAL>>>(out, out_size);
}